// round 7
// baseline (speedup 1.0000x reference)
#include <cuda_runtime.h>
#include <math_constants.h>

// Grid constants (from reference PolarVoxelizer)
#define FOV_HALF 1.134f
#define NUM_A 192
#define NUM_R 320
#define R_MIN 2.7f
#define R_MAX 165.0f
#define Z_DEPTH 100
// Problem shape (fixed per dataset)
#define SEQ 3
#define NPTS 250000
#define NB0 (SEQ * NPTS)   // 750000 batch-0 points (batch 1 never hits the output slice)

// Scratch: per-point linear index, or -1 if dropped. 3 MB static device array.
__device__ int g_lin[NB0];

// Host-side stream/events for fork-join inside graph capture (created once,
// before any capture; host resources only — no device memory).
static cudaStream_t g_s2;
static cudaEvent_t g_ev_fork, g_ev_join;
namespace {
struct PvInit {
    PvInit() {
        cudaStreamCreateWithFlags(&g_s2, cudaStreamNonBlocking);
        cudaEventCreateWithFlags(&g_ev_fork, cudaEventDisableTiming);
        cudaEventCreateWithFlags(&g_ev_join, cudaEventDisableTiming);
    }
};
static PvInit g_pv_init;
}

// ---------------------------------------------------------------------------
// Kernel 1: zero the output grid (73.7 MB). HBM-write-bound, ~11.5us measured.
// ---------------------------------------------------------------------------
__global__ void pv_zero_kernel(float4* __restrict__ out4, int n4,
                               float* __restrict__ out, int n_tail_start, int n_total) {
    int i = blockIdx.x * blockDim.x + threadIdx.x;
    if (i < n4) {
        out4[i] = make_float4(0.f, 0.f, 0.f, 0.f);
    }
    int t = n_tail_start + i;
    if (i < 4 && t < n_total) {
        out[t] = 0.f;
    }
}

// ---------------------------------------------------------------------------
// Kernel 2 (overlapped with zeroing): compute per-point linear index.
// lower_bound via estimate + 6-wide parallel window count:
//   r_bins log-spaced  -> estimate via __log2f, self-calibrated from bins
//   a_bins uniform     -> estimate via linear map, self-calibrated
// Window of 6 independent LDS with +/-2 margin; smem padded with +inf so the
// count formula k0 + sum(bins[k0+j] < v) reproduces searchsorted(side='left')
// exactly (estimate error << 1 bin).
// ---------------------------------------------------------------------------
__global__ void pv_compute_kernel(const float* __restrict__ lidars,
                                  const float* __restrict__ r_bins,
                                  const float* __restrict__ a_bins,
                                  int npts) {
    __shared__ float s_r[NUM_R + 8];
    __shared__ float s_a[NUM_A + 8];
    __shared__ float s_c[4];   // [l0_r, inv_log_r, b0_a, inv_step_a]

    for (int i = threadIdx.x; i < NUM_R + 8; i += blockDim.x)
        s_r[i] = (i < NUM_R) ? r_bins[i] : CUDART_INF_F;
    for (int i = threadIdx.x; i < NUM_A + 8; i += blockDim.x)
        s_a[i] = (i < NUM_A) ? a_bins[i] : CUDART_INF_F;
    __syncthreads();
    if (threadIdx.x == 0) {
        float l0 = __log2f(s_r[0]);
        s_c[0] = l0;
        s_c[1] = (float)(NUM_R - 1) / (__log2f(s_r[NUM_R - 1]) - l0);
        s_c[2] = s_a[0];
        s_c[3] = (float)(NUM_A - 1) / (s_a[NUM_A - 1] - s_a[0]);
    }
    __syncthreads();

    int i = blockIdx.x * blockDim.x + threadIdx.x;
    if (i >= npts) return;

    float x = lidars[3 * i + 0];
    float y = lidars[3 * i + 1];
    float z = lidars[3 * i + 2];

    // Exact same math as the verified-correct kernel (IEEE, no contraction).
    float ang = atan2f(y, x);
    float r2  = __fadd_rn(__fmul_rn(x, x), __fmul_rn(y, y));
    float rad = __fsqrt_rn(r2);

    int lin = -1;
    if ((fabsf(ang) < FOV_HALF) & (rad < R_MAX) & (rad > R_MIN)) {
        // radius bin: log-spaced estimate + window count
        float est_r = (__log2f(rad) - s_c[0]) * s_c[1];
        int k0 = (int)floorf(est_r) - 2;
        k0 = max(k0, 0);
        int xg = k0;
        #pragma unroll
        for (int j = 0; j < 6; j++) xg += (s_r[k0 + j] < rad) ? 1 : 0;

        // angle bin: uniform estimate + window count
        float est_a = (ang - s_c[2]) * s_c[3];
        int a0 = (int)floorf(est_a) - 2;
        a0 = max(a0, 0);
        int yg = a0;
        #pragma unroll
        for (int j = 0; j < 6; j++) yg += (s_a[a0 + j] < ang) ? 1 : 0;

        // z bin (IEEE div to match reference)
        int zg = (int)floorf(__fdiv_rn(__fadd_rn(z, 2.0f), 0.2f));

        if ((unsigned)zg < (unsigned)Z_DEPTH &&
            (unsigned)yg < (unsigned)NUM_A &&
            (unsigned)xg < (unsigned)NUM_R) {
            int s = i / NPTS;
            lin = (((s * Z_DEPTH + zg) * NUM_A) + yg) * NUM_R + xg;
        }
    }
    g_lin[i] = lin;
}

// ---------------------------------------------------------------------------
// Kernel 3: scatter 1.0f at precomputed indices (idempotent, no atomics).
// ---------------------------------------------------------------------------
__global__ void pv_scatter_idx_kernel(float* __restrict__ out, int n4) {
    int i = blockIdx.x * blockDim.x + threadIdx.x;
    if (i >= n4) return;
    int4 v = reinterpret_cast<const int4*>(g_lin)[i];
    if (v.x >= 0) out[v.x] = 1.0f;
    if (v.y >= 0) out[v.y] = 1.0f;
    if (v.z >= 0) out[v.z] = 1.0f;
    if (v.w >= 0) out[v.w] = 1.0f;
}

// ---------------------------------------------------------------------------
extern "C" void kernel_launch(void* const* d_in, const int* in_sizes, int n_in,
                              void* d_out, int out_size) {
    const float* lidars = (const float*)d_in[0];   // [B,S,N,3] f32
    const float* r_bins = (const float*)d_in[1];   // [320]
    const float* a_bins = (const float*)d_in[2];   // [192]
    float* out = (float*)d_out;                    // [S*Z, A, R] f32 (batch 0 slice)

    // Fork: compute (ALU-bound) runs concurrently with zeroing (HBM-bound).
    cudaEventRecord(g_ev_fork, 0);
    cudaStreamWaitEvent(g_s2, g_ev_fork, 0);

    {   // compute per-point indices on side stream
        int threads = 256;
        int blocks = (NB0 + threads - 1) / threads;
        pv_compute_kernel<<<blocks, threads, 0, g_s2>>>(lidars, r_bins, a_bins, NB0);
    }

    {   // zero the grid on main stream
        int n4 = out_size >> 2;
        int tail_start = n4 << 2;
        int threads = 256;
        int blocks = (n4 + threads - 1) / threads;
        pv_zero_kernel<<<blocks, threads>>>((float4*)out, n4, out, tail_start, out_size);
    }

    // Join: scatter needs both the zeroed grid and the computed indices.
    cudaEventRecord(g_ev_join, g_s2);
    cudaStreamWaitEvent(0, g_ev_join, 0);

    {
        int n4 = NB0 / 4;   // 750000 % 4 == 0
        int threads = 256;
        int blocks = (n4 + threads - 1) / threads;
        pv_scatter_idx_kernel<<<blocks, threads>>>(out, n4);
    }
}

// round 8
// speedup vs baseline: 1.7298x; 1.7298x over previous
#include <cuda_runtime.h>
#include <math_constants.h>

// Grid constants (from reference PolarVoxelizer)
#define FOV_HALF 1.134f
#define NUM_A 192
#define NUM_R 320
#define R_MIN 2.7f
#define R_MAX 165.0f
#define Z_DEPTH 100
// Problem shape (fixed per dataset)
#define SEQ 3
#define NPTS 250000
#define NB0 (SEQ * NPTS)          // 750000 batch-0 points (batch 1 never hits the slice)

#define TPB 256
#define NC_BLOCKS ((NB0 + TPB - 1) / TPB)     // 2930 compute blocks
#define TOTAL_BLOCKS (NC_BLOCKS * 8)          // 23440: 1-in-8 compute, 7-in-8 zero
#define NZ_BLOCKS (TOTAL_BLOCKS - NC_BLOCKS)  // 20510 zero blocks

// Scratch: per-point linear index, or -1 if dropped. 3 MB static device array.
__device__ int g_lin[NB0];

// ---------------------------------------------------------------------------
// Fused kernel: blocks with (blockIdx & 7) == 7 compute point indices into
// g_lin; all other blocks zero the output grid. The two block populations are
// co-resident on every SM: zero blocks saturate DRAM writes (tiny issue use),
// compute blocks saturate issue slots (tiny DRAM use). No ordering hazard —
// compute blocks never touch `out`.
// ---------------------------------------------------------------------------
__global__ void __launch_bounds__(TPB)
pv_fused_kernel(const float* __restrict__ lidars,
                const float* __restrict__ r_bins,
                const float* __restrict__ a_bins,
                float4* __restrict__ out4, int n4,
                float* __restrict__ out, int n_total) {
    int b = blockIdx.x;
    int tid = threadIdx.x;

    if ((b & 7) != 7) {
        // ---------------- zero role ----------------
        int zb = b - (b >> 3);                 // zero-block rank 0..NZ_BLOCKS-1
        int idx = zb * TPB + tid;              // stride covers n4 in one shot
        if (idx < n4) out4[idx] = make_float4(0.f, 0.f, 0.f, 0.f);
        // tail (out_size % 4), handled by first zero block
        if (zb == 0 && tid < 4) {
            int t = (n4 << 2) + tid;
            if (t < n_total) out[t] = 0.f;
        }
        return;
    }

    // ---------------- compute role ----------------
    __shared__ float s_r[NUM_R + 8];
    __shared__ float s_a[NUM_A + 8];
    __shared__ float s_c[4];   // [log2(r0), bins/log2-span, a0, bins/angle-span]

    for (int i = tid; i < NUM_R + 8; i += TPB)
        s_r[i] = (i < NUM_R) ? r_bins[i] : CUDART_INF_F;
    for (int i = tid; i < NUM_A + 8; i += TPB)
        s_a[i] = (i < NUM_A) ? a_bins[i] : CUDART_INF_F;
    __syncthreads();
    if (tid == 0) {
        float l0 = __log2f(s_r[0]);
        s_c[0] = l0;
        s_c[1] = (float)(NUM_R - 1) / (__log2f(s_r[NUM_R - 1]) - l0);
        s_c[2] = s_a[0];
        s_c[3] = (float)(NUM_A - 1) / (s_a[NUM_A - 1] - s_a[0]);
    }
    __syncthreads();

    int i = (b >> 3) * TPB + tid;              // point index 0..NB0-1
    if (i >= NB0) return;

    float x = lidars[3 * i + 0];
    float y = lidars[3 * i + 1];
    float z = lidars[3 * i + 2];

    // Exact same math as the verified-correct kernel (IEEE, no contraction).
    float ang = atan2f(y, x);
    float r2  = __fadd_rn(__fmul_rn(x, x), __fmul_rn(y, y));
    float rad = __fsqrt_rn(r2);

    int lin = -1;
    if ((fabsf(ang) < FOV_HALF) & (rad < R_MAX) & (rad > R_MIN)) {
        // radius bin: log-spaced estimate + 4-wide window count (margin ±1;
        // estimate error ~1e-4 bins — verified at margin 2 in a prior round)
        float est_r = (__log2f(rad) - s_c[0]) * s_c[1];
        int k0 = max((int)floorf(est_r) - 1, 0);
        int xg = k0;
        #pragma unroll
        for (int j = 0; j < 4; j++) xg += (s_r[k0 + j] < rad) ? 1 : 0;

        // angle bin: uniform estimate + 4-wide window count
        float est_a = (ang - s_c[2]) * s_c[3];
        int a0 = max((int)floorf(est_a) - 1, 0);
        int yg = a0;
        #pragma unroll
        for (int j = 0; j < 4; j++) yg += (s_a[a0 + j] < ang) ? 1 : 0;

        // z bin (IEEE div to match reference)
        int zg = (int)floorf(__fdiv_rn(__fadd_rn(z, 2.0f), 0.2f));

        if ((unsigned)zg < (unsigned)Z_DEPTH &&
            (unsigned)yg < (unsigned)NUM_A &&
            (unsigned)xg < (unsigned)NUM_R) {
            int s = i / NPTS;
            lin = (((s * Z_DEPTH + zg) * NUM_A) + yg) * NUM_R + xg;
        }
    }
    g_lin[i] = lin;
}

// ---------------------------------------------------------------------------
// Scatter 1.0f at precomputed indices (idempotent -> plain stores, no atomics).
// g_lin is L2-hot from the fused kernel; ~270k scattered 4B stores.
// ---------------------------------------------------------------------------
__global__ void __launch_bounds__(TPB)
pv_scatter_idx_kernel(float* __restrict__ out, int n4) {
    int i = blockIdx.x * blockDim.x + threadIdx.x;
    if (i >= n4) return;
    int4 v = reinterpret_cast<const int4*>(g_lin)[i];
    if (v.x >= 0) out[v.x] = 1.0f;
    if (v.y >= 0) out[v.y] = 1.0f;
    if (v.z >= 0) out[v.z] = 1.0f;
    if (v.w >= 0) out[v.w] = 1.0f;
}

// ---------------------------------------------------------------------------
extern "C" void kernel_launch(void* const* d_in, const int* in_sizes, int n_in,
                              void* d_out, int out_size) {
    const float* lidars = (const float*)d_in[0];   // [B,S,N,3] f32
    const float* r_bins = (const float*)d_in[1];   // [320]
    const float* a_bins = (const float*)d_in[2];   // [192]
    float* out = (float*)d_out;                    // [S*Z, A, R] f32 (batch 0 slice)

    int n4 = out_size >> 2;

    pv_fused_kernel<<<TOTAL_BLOCKS, TPB>>>(lidars, r_bins, a_bins,
                                           (float4*)out, n4, out, out_size);

    int n4p = NB0 / 4;   // 750000 % 4 == 0
    pv_scatter_idx_kernel<<<(n4p + TPB - 1) / TPB, TPB>>>(out, n4p);
}